// round 17
// baseline (speedup 1.0000x reference)
#include <cuda_runtime.h>
#include <cuda_fp16.h>
#include <math.h>
#include <stdint.h>

#define BSZ   8
#define NSEQ  1024
#define DIMM  512
#define NH    8
#define HD    64
#define COLS3 1536
#define MROWS (BSZ*NSEQ)

// All operands pure fp16 (fp32 accumulation everywhere).
// Bias pre-converted to fp16 scaled by log2(e)  (base-2 softmax).
__device__ __align__(16) __half g_xh[MROWS*DIMM];
__device__ __align__(16) __half g_wqh[DIMM*COLS3];
__device__ __align__(16) __half g_woh[DIMM*DIMM];
__device__ __align__(16) __half g_bh[NH*NSEQ*NSEQ];
__device__ __align__(16) __half g_qh[MROWS*DIMM];
__device__ __align__(16) __half g_kh[MROWS*DIMM];
__device__ __align__(16) __half g_vh[MROWS*DIMM];
__device__ __align__(16) __half g_aoh[MROWS*DIMM];

// ---------------------------------------------------------------------------
// helpers
// ---------------------------------------------------------------------------
__device__ __forceinline__ uint32_t smem_u32(const void* p) {
    return (uint32_t)__cvta_generic_to_shared(p);
}
__device__ __forceinline__ void ldsm_x4(uint32_t& r0, uint32_t& r1,
                                        uint32_t& r2, uint32_t& r3, uint32_t a) {
    asm volatile("ldmatrix.sync.aligned.m8n8.x4.shared.b16 {%0,%1,%2,%3}, [%4];\n"
                 : "=r"(r0), "=r"(r1), "=r"(r2), "=r"(r3) : "r"(a));
}
__device__ __forceinline__ void ldsm_x4_t(uint32_t& r0, uint32_t& r1,
                                          uint32_t& r2, uint32_t& r3, uint32_t a) {
    asm volatile("ldmatrix.sync.aligned.m8n8.x4.trans.shared.b16 {%0,%1,%2,%3}, [%4];\n"
                 : "=r"(r0), "=r"(r1), "=r"(r2), "=r"(r3) : "r"(a));
}
__device__ __forceinline__ void mma2(float c[4], const uint32_t a[4],
                                     uint32_t b0, uint32_t b1) {
    asm volatile(
        "mma.sync.aligned.m16n8k16.row.col.f32.f16.f16.f32 "
        "{%0,%1,%2,%3}, {%4,%5,%6,%7}, {%8,%9}, {%0,%1,%2,%3};\n"
        : "+f"(c[0]), "+f"(c[1]), "+f"(c[2]), "+f"(c[3])
        : "r"(a[0]), "r"(a[1]), "r"(a[2]), "r"(a[3]), "r"(b0), "r"(b1));
}
__device__ __forceinline__ uint32_t pkh2(__half a, __half b) {
    __half2 t = __halves2half2(a, b);
    return *reinterpret_cast<uint32_t*>(&t);
}
__device__ __forceinline__ float ex2(float x) {      // base-2 exp (MUFU.EX2)
    float r;
    asm("ex2.approx.f32 %0, %1;" : "=f"(r) : "f"(x));
    return r;
}
#define CP16(dst, src) \
    asm volatile("cp.async.cg.shared.global [%0], [%1], 16;\n" :: "r"(dst), "l"(src))
#define CPCOMMIT() asm volatile("cp.async.commit_group;\n")
#define CPWAIT0()  asm volatile("cp.async.wait_group 0;\n")
#define CPWAIT1()  asm volatile("cp.async.wait_group 1;\n")

#define LOG2E 1.4426950408889634f

// ---------------------------------------------------------------------------
// Merged fp32 -> fp16 conversion for x, w_qkv, w_out, bias (one launch).
// Bias is scaled by log2(e) for base-2 softmax.
// ---------------------------------------------------------------------------
#define N4_X  (MROWS*DIMM/4)
#define N4_WQ (DIMM*COLS3/4)
#define N4_WO (DIMM*DIMM/4)
#define N4_B  (NH*NSEQ*NSEQ/4)
__global__ __launch_bounds__(256) void k_split_all(const float* __restrict__ x,
                                                   const float* __restrict__ wq,
                                                   const float* __restrict__ wo,
                                                   const float* __restrict__ pb) {
    int i = blockIdx.x * blockDim.x + threadIdx.x;
    const float* s;
    __half* hi;
    int j;
    float scale = 1.f;
    if (i < N4_X)                       { s = x;  hi = g_xh;  j = i; }
    else if (i < N4_X + N4_WQ)          { s = wq; hi = g_wqh; j = i - N4_X; }
    else if (i < N4_X + N4_WQ + N4_WO)  { s = wo; hi = g_woh; j = i - N4_X - N4_WQ; }
    else if (i < N4_X + N4_WQ + N4_WO + N4_B) {
        s = pb; hi = g_bh; j = i - N4_X - N4_WQ - N4_WO; scale = LOG2E;
    }
    else return;
    float4 v = ((const float4*)s)[j];
    __half h[4] = {__float2half_rn(v.x * scale), __float2half_rn(v.y * scale),
                   __float2half_rn(v.z * scale), __float2half_rn(v.w * scale)};
    ((uint2*)hi)[j] = *(const uint2*)h;
}

// ---------------------------------------------------------------------------
// GEMM: pure fp16 operands, fp32 accum. 128x128 block, 8 warps (2x4),
// KC=64 (8 chunks), 3-stage cp.async ring, 2 CTAs/SM.
// QKV epilogue: q scaled by 0.125*log2(e)  (base-2 softmax), then RoPE.
// ---------------------------------------------------------------------------
#define AST 72
#define BST 136
#define G_ASTAGE (128*AST)
#define G_BSTAGE (64*BST)
#define G_STAGE  (G_ASTAGE + G_BSTAGE)       // 17920 halves = 35840 B
#define GEMM_SMEM (3 * G_STAGE * 2)          // 107520 B

template<int NC, bool QKV>
__global__ __launch_bounds__(256, 2) void gemm_mma(float* __restrict__ Og) {
    constexpr int KD = 512;
    constexpr int NKC = KD / 64;
    extern __shared__ __half sg[];

    const int tid  = threadIdx.x;
    const int lane = tid & 31;
    const int wid  = tid >> 5;
    const int wm   = wid >> 2;
    const int wn   = wid & 3;
    const int row0 = blockIdx.y * 128;
    const int col0 = blockIdx.x * 128;
    const int lrow = lane & 15;
    const int lko  = (lane >> 4) * 8;

    float C[4][4][4];
#pragma unroll
    for (int i = 0; i < 4; i++)
#pragma unroll
        for (int j = 0; j < 4; j++)
#pragma unroll
            for (int e = 0; e < 4; e++) C[i][j][e] = 0.f;

    const __half* Ahg = QKV ? g_xh : g_aoh;
    const __half* Bhg = QKV ? g_wqh : g_woh;

    auto prefetch = [&](int sbase, int kk) {
#pragma unroll
        for (int i = 0; i < 4; i++) {
            int cid = tid + 256 * i;
            int row = cid >> 3, ch = cid & 7;
            CP16(smem_u32(&sg[sbase + row * AST + ch * 8]),
                 Ahg + (size_t)(row0 + row) * KD + kk + ch * 8);
        }
#pragma unroll
        for (int i = 0; i < 4; i++) {
            int cid = tid + 256 * i;
            int row = cid >> 4, ch = cid & 15;
            CP16(smem_u32(&sg[sbase + G_ASTAGE + row * BST + ch * 8]),
                 Bhg + (size_t)(kk + row) * NC + col0 + ch * 8);
        }
        CPCOMMIT();
    };

    prefetch(0, 0);
    prefetch(G_STAGE, 64);

    for (int kc = 0; kc < NKC; kc++) {
        CPWAIT1();
        __syncthreads();
        if (kc + 2 < NKC) prefetch(((kc + 2) % 3) * G_STAGE, (kc + 2) * 64);
        else CPCOMMIT();

        const __half* Ahs = sg + (kc % 3) * G_STAGE;
        const __half* Bhs = Ahs + G_ASTAGE;

#pragma unroll
        for (int kq = 0; kq < 64; kq += 16) {
            uint32_t aH[4][4];
#pragma unroll
            for (int mt = 0; mt < 4; mt++) {
                int r = wm * 64 + mt * 16 + lrow;
                ldsm_x4(aH[mt][0], aH[mt][1], aH[mt][2], aH[mt][3],
                        smem_u32(&Ahs[r * AST + kq + lko]));
            }
            int rr = kq + lrow;
#pragma unroll
            for (int ng = 0; ng < 2; ng++) {
                uint32_t bH[4];
                int cb = wn * 32 + ng * 16 + lko;
                ldsm_x4_t(bH[0], bH[1], bH[2], bH[3], smem_u32(&Bhs[rr * BST + cb]));
#pragma unroll
                for (int mt = 0; mt < 4; mt++)
                    mma2(C[mt][ng*2],     aH[mt], bH[0], bH[1]);
#pragma unroll
                for (int mt = 0; mt < 4; mt++)
                    mma2(C[mt][ng*2 + 1], aH[mt], bH[2], bH[3]);
            }
        }
    }

    const int g  = lane >> 2;
    const int cc = (lane & 3) * 2;
    if (QKV) {
        const int sec     = col0 >> 9;
        const int rembase = (col0 & 511) + wn * 32;
        __half* dsth = (sec == 0) ? g_qh : (sec == 1 ? g_kh : g_vh);
        const float LOG2B = 13.287712379549449f;
        const float QSC   = 0.125f * LOG2E;      // base-2 softmax pre-scale
#pragma unroll
        for (int nt = 0; nt < 4; nt++) {
            int rem   = rembase + nt * 8 + cc;
            int h     = rem >> 6;
            int dbase = rem & 63;
            float ifr = exp2f(-(float)dbase * (LOG2B / 64.f));
#pragma unroll
            for (int mt = 0; mt < 4; mt++) {
#pragma unroll
                for (int hf = 0; hf < 2; hf++) {
                    int R = row0 + wm * 64 + mt * 16 + g + hf * 8;
                    int b = R >> 10, n = R & 1023;
                    float v0 = C[mt][nt][hf*2 + 0];
                    float v1 = C[mt][nt][hf*2 + 1];
                    if (sec == 0) { v0 *= QSC; v1 *= QSC; }
                    if (sec < 2) {
                        float s, co;
                        sincosf((float)n * ifr, &s, &co);
                        float t0 = v0 * co - v1 * s;
                        float t1 = v1 * co + v0 * s;
                        v0 = t0; v1 = t1;
                    }
                    size_t idx = (((size_t)b * NH + h) * NSEQ + n) * HD + dbase;
                    *(__half2*)&dsth[idx] = __halves2half2(
                        __float2half_rn(v0), __float2half_rn(v1));
                }
            }
        }
    } else {
#pragma unroll
        for (int nt = 0; nt < 4; nt++) {
            int colg = col0 + wn * 32 + nt * 8 + cc;
#pragma unroll
            for (int mt = 0; mt < 4; mt++) {
#pragma unroll
                for (int hf = 0; hf < 2; hf++) {
                    int R = row0 + wm * 64 + mt * 16 + g + hf * 8;
                    *(float2*)&Og[(size_t)R * NC + colg] =
                        make_float2(C[mt][nt][hf*2], C[mt][nt][hf*2 + 1]);
                }
            }
        }
    }
}

// ---------------------------------------------------------------------------
// Flash attention, base-2 softmax: S2 = (q*0.125+bias)*log2e accumulated via
// pre-scaled q and bias; P = ex2(S2 - m2). Pure fp16 operands, 2 CTAs/SM,
// 3-stage KV ring, one sync per tile. Bias loaded as fp16.
// ---------------------------------------------------------------------------
#define QST 72
#define STAGE_H (2 * 64 * QST)
#define ATTN_SMEM (3 * STAGE_H * 2)      // 55296 B

__global__ __launch_bounds__(256, 2) void k_attn_mma() {
    extern __shared__ __half sm[];

    const int b  = blockIdx.x;      // fastest: batches share bias slice in L2
    const int h  = blockIdx.y;
    const int i0 = blockIdx.z * 128;
    const int tid = threadIdx.x, lane = tid & 31, w = tid >> 5;
    const int lrow = lane & 15, lko = (lane >> 4) * 8;
    const int g = lane >> 2, c2 = (lane & 3) * 2;

    const size_t bh = (size_t)(b * NH + h) * NSEQ * HD;
    const __half* kv_src[2] = {g_kh + bh, g_vh + bh};
    const __half* bgh = g_bh + (size_t)h * NSEQ * NSEQ;

    // ---- stage Q through stage0 (overwritten later), extract frags ----
    {
        const __half* qh = g_qh + bh;
#pragma unroll
        for (int i = 0; i < 4; i++) {
            int cid = tid + 256 * i;
            int row = cid >> 3, ch = cid & 7;
            CP16(smem_u32(&sm[row * QST + ch * 8]),
                 qh + (size_t)(i0 + row) * HD + ch * 8);
        }
        CPCOMMIT();
        CPWAIT0();
        __syncthreads();
    }
    uint32_t qH[4][4];
#pragma unroll
    for (int ks = 0; ks < 4; ks++)
        ldsm_x4(qH[ks][0], qH[ks][1], qH[ks][2], qH[ks][3],
                smem_u32(&sm[(w*16 + lrow)*QST + ks*16 + lko]));
    __syncthreads();

    auto kvload = [&](int sbase, int j0) {
#pragma unroll
        for (int i = 0; i < 4; i++) {
            int cid = tid + 256 * i;
            int arr = cid >> 9;
            int rem = cid & 511;
            int row = rem >> 3, ch = rem & 7;
            CP16(smem_u32(&sm[sbase + arr * 64 * QST + row * QST + ch * 8]),
                 kv_src[arr] + (size_t)(j0 + row) * HD + ch * 8);
        }
        CPCOMMIT();
    };

    kvload(0, 0);
    kvload(STAGE_H, 64);

    float Of[8][4];
#pragma unroll
    for (int nt = 0; nt < 8; nt++)
#pragma unroll
        for (int e = 0; e < 4; e++) Of[nt][e] = 0.f;
    float m0 = -INFINITY, m1 = -INFINITY, l0 = 0.f, l1 = 0.f;
    const int r0g = i0 + w * 16 + g;

    for (int jt = 0; jt < 16; jt++) {
        CPWAIT1();
        __syncthreads();
        if (jt + 2 < 16) kvload(((jt + 2) % 3) * STAGE_H, (jt + 2) * 64);
        else CPCOMMIT();

        const __half* st = sm + (jt % 3) * STAGE_H;
        const int j0 = jt * 64;

        // bias prefetch (fp16, 2 values per load)
        uint32_t bu[8], bw[8];
        {
            const __half* bp0 = bgh + (size_t)r0g * NSEQ + j0 + c2;
            const __half* bp1 = bp0 + 8 * NSEQ;
#pragma unroll
            for (int nt = 0; nt < 8; nt++) {
                bu[nt] = *(const uint32_t*)(bp0 + nt * 8);
                bw[nt] = *(const uint32_t*)(bp1 + nt * 8);
            }
        }

        // ---- S2 = qH * kH (q pre-scaled by 0.125*log2e) ----
        float Sf[8][4];
#pragma unroll
        for (int nt = 0; nt < 8; nt++)
#pragma unroll
            for (int e = 0; e < 4; e++) Sf[nt][e] = 0.f;
#pragma unroll
        for (int ks = 0; ks < 4; ks++) {
#pragma unroll
            for (int ng = 0; ng < 4; ng++) {
                uint32_t kh_[4];
                ldsm_x4(kh_[0], kh_[1], kh_[2], kh_[3],
                        smem_u32(&st[(ng*16 + lrow)*QST + ks*16 + lko]));
                mma2(Sf[2*ng],   qH[ks], kh_[0], kh_[2]);
                mma2(Sf[2*ng+1], qH[ks], kh_[1], kh_[3]);
            }
        }
#pragma unroll
        for (int nt = 0; nt < 8; nt++) {
            float2 u = __half22float2(*(const __half2*)&bu[nt]);
            float2 v = __half22float2(*(const __half2*)&bw[nt]);
            Sf[nt][0] += u.x; Sf[nt][1] += u.y;
            Sf[nt][2] += v.x; Sf[nt][3] += v.y;
        }

        // ---- online softmax (base-2) ----
        float mx0 = -INFINITY, mx1 = -INFINITY;
#pragma unroll
        for (int nt = 0; nt < 8; nt++) {
            mx0 = fmaxf(mx0, fmaxf(Sf[nt][0], Sf[nt][1]));
            mx1 = fmaxf(mx1, fmaxf(Sf[nt][2], Sf[nt][3]));
        }
        mx0 = fmaxf(mx0, __shfl_xor_sync(0xffffffffu, mx0, 1));
        mx0 = fmaxf(mx0, __shfl_xor_sync(0xffffffffu, mx0, 2));
        mx1 = fmaxf(mx1, __shfl_xor_sync(0xffffffffu, mx1, 1));
        mx1 = fmaxf(mx1, __shfl_xor_sync(0xffffffffu, mx1, 2));
        float mn0 = fmaxf(m0, mx0), mn1 = fmaxf(m1, mx1);
        float rs0 = ex2(m0 - mn0), rs1 = ex2(m1 - mn1);
        m0 = mn0; m1 = mn1;

        uint32_t pH0[8], pH1[8];
        float s0 = 0.f, s1 = 0.f;
#pragma unroll
        for (int nt = 0; nt < 8; nt++) {
            float p0 = ex2(Sf[nt][0] - mn0);
            float p1 = ex2(Sf[nt][1] - mn0);
            float p2 = ex2(Sf[nt][2] - mn1);
            float p3 = ex2(Sf[nt][3] - mn1);
            s0 += p0 + p1; s1 += p2 + p3;
            pH0[nt] = pkh2(__float2half_rn(p0), __float2half_rn(p1));
            pH1[nt] = pkh2(__float2half_rn(p2), __float2half_rn(p3));
        }
        s0 += __shfl_xor_sync(0xffffffffu, s0, 1);
        s0 += __shfl_xor_sync(0xffffffffu, s0, 2);
        s1 += __shfl_xor_sync(0xffffffffu, s1, 1);
        s1 += __shfl_xor_sync(0xffffffffu, s1, 2);
        l0 = l0 * rs0 + s0;
        l1 = l1 * rs1 + s1;
#pragma unroll
        for (int nt = 0; nt < 8; nt++) {
            Of[nt][0] *= rs0; Of[nt][1] *= rs0;
            Of[nt][2] *= rs1; Of[nt][3] *= rs1;
        }

        // ---- O += pH * vH ----
#pragma unroll
        for (int ks = 0; ks < 4; ks++) {
            uint32_t aH[4] = {pH0[2*ks], pH1[2*ks], pH0[2*ks+1], pH1[2*ks+1]};
#pragma unroll
            for (int dg = 0; dg < 4; dg++) {
                uint32_t vh_[4];
                ldsm_x4_t(vh_[0], vh_[1], vh_[2], vh_[3],
                          smem_u32(&st[64*QST + (ks*16 + lrow)*QST + dg*16 + lko]));
                mma2(Of[2*dg],   aH, vh_[0], vh_[1]);
                mma2(Of[2*dg+1], aH, vh_[2], vh_[3]);
            }
        }
    }

    // ---- normalize + store hi-only O to g_aoh [B,N,H*D] ----
    {
        float inv0 = 1.f / l0, inv1 = 1.f / l1;
        size_t base0 = ((size_t)b * NSEQ + r0g) * DIMM + h * HD + c2;
        size_t base1 = base0 + 8 * DIMM;
#pragma unroll
        for (int nt = 0; nt < 8; nt++) {
            *(__half2*)&g_aoh[base0 + nt*8] = __halves2half2(
                __float2half_rn(Of[nt][0] * inv0), __float2half_rn(Of[nt][1] * inv0));
            *(__half2*)&g_aoh[base1 + nt*8] = __halves2half2(
                __float2half_rn(Of[nt][2] * inv1), __float2half_rn(Of[nt][3] * inv1));
        }
    }
}

// ---------------------------------------------------------------------------
extern "C" void kernel_launch(void* const* d_in, const int* in_sizes, int n_in,
                              void* d_out, int out_size) {
    const float *x = nullptr, *pb = nullptr, *wq = nullptr, *wo = nullptr;
    for (int i = 0; i < n_in; i++) {
        switch (in_sizes[i]) {
            case 4194304: x  = (const float*)d_in[i]; break;  // x [8,1024,512]
            case 8388608: pb = (const float*)d_in[i]; break;  // pos_bias [8,1024,1024]
            case 786432:  wq = (const float*)d_in[i]; break;  // w_qkv [512,1536]
            case 262144:  wo = (const float*)d_in[i]; break;  // w_out [512,512]
        }
    }
    if (!x)  x  = (const float*)d_in[0];
    if (!pb) pb = (const float*)d_in[1];
    if (!wq) wq = (const float*)d_in[2];
    if (!wo) wo = (const float*)d_in[3];

    cudaFuncSetAttribute(k_attn_mma, cudaFuncAttributeMaxDynamicSharedMemorySize,
                         ATTN_SMEM);
    cudaFuncSetAttribute(gemm_mma<COLS3, true>,
                         cudaFuncAttributeMaxDynamicSharedMemorySize, GEMM_SMEM);
    cudaFuncSetAttribute(gemm_mma<DIMM, false>,
                         cudaFuncAttributeMaxDynamicSharedMemorySize, GEMM_SMEM);

    const int n4tot = N4_X + N4_WQ + N4_WO + N4_B;
    k_split_all<<<(n4tot + 255) / 256, 256>>>(x, wq, wo, pb);

    gemm_mma<COLS3, true><<<dim3(12, 64), 256, GEMM_SMEM>>>(nullptr);
    k_attn_mma<<<dim3(BSZ, NH, 8), 256, ATTN_SMEM>>>();
    gemm_mma<DIMM, false><<<dim3(4, 64), 256, GEMM_SMEM>>>((float*)d_out);
}